// round 10
// baseline (speedup 1.0000x reference)
#include <cuda_runtime.h>

#define TWO_PI_F 6.283185307179586f
#define NROT 8
#define C_DIM 128
#define KS 5
#define PATCH 25
#define TPB 256
#define CIN_CHUNK 32
#define NACT 13
#define OGRP 8
#define ACT_MASK 0x477DC4u          // bit p set iff X^2+Y^2 <= 1 on 5x5 grid
#define OUT_CI_STRIDE (NROT * C_DIM * 200)   // 204800
#define WPAD 105                    // wbil row stride (105 % 32 = 9, conflict-free)

__device__ __constant__ int APLIST[NACT] = {2,6,7,8,10,11,12,13,14,16,17,18,22};

__device__ __forceinline__ unsigned smem_u32(const void* p) {
    return (unsigned)__cvta_generic_to_shared(p);
}

__global__ __launch_bounds__(TPB, 5)
void gk_r10_kernel(const float* __restrict__ in_H,
                   const float* __restrict__ out_H,
                   const float* __restrict__ weight,
                   float* __restrict__ out)
{
    __shared__ float    slab[NROT * 800];        // 25.6 KB  [g][ci32][q25]
    __shared__ float    wbil[CIN_CHUNK * WPAD];  // 13.44 KB [ci][g*13+pa]
    __shared__ float    ftab[OGRP * 8];          // frac per (oo,i)
    __shared__ int      gtab[OGRP * 8];          // g0 per (oo,i)
    __shared__ float4   ctab[OGRP * NACT];
    __shared__ int4     qtab[OGRP * NACT];
    __shared__ float    frtab[224];              // per-oo per-r frac
    __shared__ unsigned offtab[224];             // per-oo per-r: off0|off1<<8|act<<16

    const int co      = blockIdx.x;
    const int ci_base = blockIdx.y * CIN_CHUNK;
    const int tid     = threadIdx.x;
    const int w       = tid >> 5;
    const int lane    = tid & 31;

    // ---- fill slab with cp.async (one load serves all 8 o's) ----
    {
        const float4* __restrict__ w4 = (const float4*)weight;
#pragma unroll
        for (int k = 0; k < 7; ++k) {
            int f = tid + k * TPB;                   // float4 index 0..1599
            if (f < 1600) {
                int g = f / 200;
                int r = f - g * 200;
                size_t gb4 = ((size_t)((g * C_DIM + co) * C_DIM + ci_base) * PATCH) >> 2;
                unsigned dst = smem_u32(&slab[g * 800 + r * 4]);
                asm volatile("cp.async.cg.shared.global [%0], [%1], 16;\n"
                             :: "r"(dst), "l"(w4 + gb4 + r) : "memory");
            }
        }
        asm volatile("cp.async.commit_group;\n" ::: "memory");
    }

    // ---- per-(oo,i) Gk lerp table (all 8 oo upfront) ----
    if (tid < OGRP * 8) {
        const int oo = tid >> 3, i = tid & 7;
        const float outH  = out_H[oo];
        const float theta = in_H[i] - outH;
        const float tmod  = theta - floorf(theta * (1.0f / TWO_PI_F)) * TWO_PI_F;
        const float pos   = tmod * ((float)NROT / TWO_PI_F);
        int g0 = ((int)floorf(pos)) % NROT;
        if (g0 >= NROT) g0 -= NROT;
        ftab[tid] = pos - floorf(pos);
        gtab[tid] = g0;
    }

    // ---- per-(oo,pa) bilinear tables (all 8 oo upfront) ----
    if (tid < OGRP * NACT) {
        const int oo = tid / NACT, pa = tid - oo * NACT;
        const int p  = APLIST[pa];
        const int px = p % KS, py = p / KS;
        const float X = -1.0f + 0.5f * (float)px;
        const float Y = -1.0f + 0.5f * (float)py;
        const float outH = out_H[oo];
        const float cc = cosf(-outH), ss = sinf(-outH);
        const float gx = cc * X - ss * Y;
        const float gy = ss * X + cc * Y;
        const float sx = fmaf(gx, 2.0f, 2.0f);
        const float sy = fmaf(gy, 2.0f, 2.0f);
        const float fxf = floorf(sx), fyf = floorf(sy);
        const float fx = sx - fxf, fy = sy - fyf;
        int x0 = min(max((int)fxf, 0), KS - 1);
        int y0 = min(max((int)fyf, 0), KS - 1);
        const int x1 = min(x0 + 1, KS - 1);
        const int y1 = min(y0 + 1, KS - 1);
        ctab[tid] = make_float4((1.0f - fy) * (1.0f - fx), (1.0f - fy) * fx,
                                fy * (1.0f - fx),          fy * fx);
        qtab[tid] = make_int4(y0 * KS + x0, y0 * KS + x1,
                              y1 * KS + x0, y1 * KS + x1);
    }

    asm volatile("cp.async.wait_group 0;\n" ::: "memory");
    __syncthreads();

    for (int oo = 0; oo < OGRP; ++oo) {
        // ---- (a) build per-oo BC tables (200 threads, trivial) ----
        if (tid < 200) {
            const int r  = tid;
            const int ii = r / 25;
            const int p  = r - ii * 25;
            const int pa = __popc(ACT_MASK & ((1u << p) - 1u));
            const int t  = oo * 8 + ii;
            const int g0 = gtab[t];
            const int g1 = (g0 + 1) & (NROT - 1);
            const unsigned act = (ACT_MASK >> p) & 1u;
            frtab[r]  = ftab[t];
            offtab[r] = (unsigned)(g0 * NACT + pa)
                      | ((unsigned)(g1 * NACT + pa) << 8)
                      | (act << 16);
        }

        // ---- (b) phase A: bilinear gather per g-slab -> wbil[ci][g*13+pa] ----
        {
            const float* srow = slab + w * 800 + lane * PATCH;   // stride 25: CF
            float* wrow = wbil + lane * WPAD + w * NACT;
#pragma unroll
            for (int pa = 0; pa < NACT; ++pa) {
                const int4   q = qtab[oo * NACT + pa];   // broadcast
                const float4 c = ctab[oo * NACT + pa];   // broadcast
                float v;
                v = c.x * srow[q.x];
                v = fmaf(c.y, srow[q.y], v);
                v = fmaf(c.z, srow[q.z], v);
                v = fmaf(c.w, srow[q.w], v);
                wrow[pa] = v;                            // stride 105: CF
            }
        }
        __syncthreads();

        // ---- (c) phase BC: rc-outer, table-driven, hoisted cj pointers ----
        {
            const float* wr0 = wbil + (w +  0) * WPAD;
            const float* wr1 = wbil + (w +  8) * WPAD;
            const float* wr2 = wbil + (w + 16) * WPAD;
            const float* wr3 = wbil + (w + 24) * WPAD;
            float* ob = out + (size_t)ci_base * OUT_CI_STRIDE
                            + (size_t)(oo * C_DIM + co) * 200
                            + (size_t)w * OUT_CI_STRIDE;
            float* o0p = ob;
            float* o1p = ob + (size_t)8  * OUT_CI_STRIDE;
            float* o2p = ob + (size_t)16 * OUT_CI_STRIDE;
            float* o3p = ob + (size_t)24 * OUT_CI_STRIDE;

#pragma unroll
            for (int rc = 0; rc < 7; ++rc) {
                const int r = rc * 32 + lane;
                if (r < 200) {
                    const float    fr = frtab[r];        // CF LDS
                    const unsigned pk = offtab[r];       // CF LDS
                    const int a0 = pk & 255;
                    const int a1 = (pk >> 8) & 255;
                    if (pk >> 16) {
                        float v0, v1;
                        v0 = wr0[a0]; v1 = wr0[a1];
                        o0p[r] = fmaf(fr, v1 - v0, v0);
                        v0 = wr1[a0]; v1 = wr1[a1];
                        o1p[r] = fmaf(fr, v1 - v0, v0);
                        v0 = wr2[a0]; v1 = wr2[a1];
                        o2p[r] = fmaf(fr, v1 - v0, v0);
                        v0 = wr3[a0]; v1 = wr3[a1];
                        o3p[r] = fmaf(fr, v1 - v0, v0);
                    } else {
                        o0p[r] = 0.0f; o1p[r] = 0.0f;
                        o2p[r] = 0.0f; o3p[r] = 0.0f;
                    }
                }
            }
        }
        __syncthreads();   // wbil + tables reused next oo
    }
}

extern "C" void kernel_launch(void* const* d_in, const int* in_sizes, int n_in,
                              void* d_out, int out_size)
{
    const float* in_H   = (const float*)d_in[0];
    const float* out_H  = (const float*)d_in[1];
    const float* weight = (const float*)d_in[2];
    float* out = (float*)d_out;

    dim3 grid(C_DIM, C_DIM / CIN_CHUNK, 1);   // 512 blocks, single wave
    gk_r10_kernel<<<grid, TPB>>>(in_H, out_H, weight, out);
}

// round 12
// speedup vs baseline: 1.1543x; 1.1543x over previous
#include <cuda_runtime.h>

#define TWO_PI_F 6.283185307179586f
#define NROT 8
#define C_DIM 128
#define KS 5
#define PATCH 25
#define TPB 256
#define CIN_CHUNK 32
#define NACT 13
#define OGRP 4
#define ACT_MASK 0x477DC4u          // bit p set iff X^2+Y^2 <= 1 on 5x5 grid
#define OUT_CI_STRIDE (NROT * C_DIM * 200)   // 204800
#define WPAD 105                    // wbil row stride (105 % 32 = 9, conflict-free)

__device__ __constant__ int APLIST[NACT] = {2,6,7,8,10,11,12,13,14,16,17,18,22};

__device__ __forceinline__ unsigned smem_u32(const void* p) {
    return (unsigned)__cvta_generic_to_shared(p);
}

__global__ __launch_bounds__(TPB, 5)
void gk_r11_kernel(const float* __restrict__ in_H,
                   const float* __restrict__ out_H,
                   const float* __restrict__ weight,
                   float* __restrict__ out)
{
    __shared__ float    slab[NROT * 800];        // 25.6 KB  [g][ci32][q25]
    __shared__ float    wbil[CIN_CHUNK * WPAD];  // 13.44 KB [ci][g*13+pa]
    __shared__ float    ftab[OGRP * 8];          // frac per (oo,i)
    __shared__ int      gtab[OGRP * 8];          // g0 per (oo,i)
    __shared__ float4   ctab[OGRP * NACT];
    __shared__ int4     qtab[OGRP * NACT];
    __shared__ float    frtab[224];              // per-oo per-r frac
    __shared__ unsigned offtab[224];             // per-oo per-r: off0|off1<<8|act<<16

    const int co      = blockIdx.x;
    const int ci_base = blockIdx.y * CIN_CHUNK;
    const int o_base  = blockIdx.z * OGRP;
    const int tid     = threadIdx.x;
    const int w       = tid >> 5;
    const int lane    = tid & 31;

    // ---- fill slab with cp.async ----
    {
        const float4* __restrict__ w4 = (const float4*)weight;
#pragma unroll
        for (int k = 0; k < 7; ++k) {
            int f = tid + k * TPB;                   // float4 index 0..1599
            if (f < 1600) {
                int g = f / 200;
                int r = f - g * 200;
                size_t gb4 = ((size_t)((g * C_DIM + co) * C_DIM + ci_base) * PATCH) >> 2;
                unsigned dst = smem_u32(&slab[g * 800 + r * 4]);
                asm volatile("cp.async.cg.shared.global [%0], [%1], 16;\n"
                             :: "r"(dst), "l"(w4 + gb4 + r) : "memory");
            }
        }
        asm volatile("cp.async.commit_group;\n" ::: "memory");
    }

    // ---- per-(oo,i) Gk lerp table ----
    if (tid < OGRP * 8) {
        const int oo = tid >> 3, i = tid & 7;
        const float outH  = out_H[o_base + oo];
        const float theta = in_H[i] - outH;
        const float tmod  = theta - floorf(theta * (1.0f / TWO_PI_F)) * TWO_PI_F;
        const float pos   = tmod * ((float)NROT / TWO_PI_F);
        int g0 = ((int)floorf(pos)) % NROT;
        if (g0 >= NROT) g0 -= NROT;
        ftab[tid] = pos - floorf(pos);
        gtab[tid] = g0;
    }

    // ---- per-(oo,pa) bilinear tables ----
    if (tid < OGRP * NACT) {
        const int oo = tid / NACT, pa = tid - oo * NACT;
        const int p  = APLIST[pa];
        const int px = p % KS, py = p / KS;
        const float X = -1.0f + 0.5f * (float)px;
        const float Y = -1.0f + 0.5f * (float)py;
        const float outH = out_H[o_base + oo];
        const float cc = cosf(-outH), ss = sinf(-outH);
        const float gx = cc * X - ss * Y;
        const float gy = ss * X + cc * Y;
        const float sx = fmaf(gx, 2.0f, 2.0f);
        const float sy = fmaf(gy, 2.0f, 2.0f);
        const float fxf = floorf(sx), fyf = floorf(sy);
        const float fx = sx - fxf, fy = sy - fyf;
        int x0 = min(max((int)fxf, 0), KS - 1);
        int y0 = min(max((int)fyf, 0), KS - 1);
        const int x1 = min(x0 + 1, KS - 1);
        const int y1 = min(y0 + 1, KS - 1);
        ctab[tid] = make_float4((1.0f - fy) * (1.0f - fx), (1.0f - fy) * fx,
                                fy * (1.0f - fx),          fy * fx);
        qtab[tid] = make_int4(y0 * KS + x0, y0 * KS + x1,
                              y1 * KS + x0, y1 * KS + x1);
    }

    asm volatile("cp.async.wait_group 0;\n" ::: "memory");
    __syncthreads();

    for (int oo = 0; oo < OGRP; ++oo) {
        // ---- (a) per-oo BC tables ----
        if (tid < 200) {
            const int r  = tid;
            const int ii = r / 25;
            const int p  = r - ii * 25;
            const int pa = __popc(ACT_MASK & ((1u << p) - 1u));
            const int t  = oo * 8 + ii;
            const int g0 = gtab[t];
            const int g1 = (g0 + 1) & (NROT - 1);
            const unsigned act = (ACT_MASK >> p) & 1u;
            frtab[r]  = ftab[t];
            offtab[r] = (unsigned)(g0 * NACT + pa)
                      | ((unsigned)(g1 * NACT + pa) << 8)
                      | (act << 16);
        }

        // ---- (b) phase A: bilinear gather per g-slab -> wbil[ci][g*13+pa] ----
        {
            const float* srow = slab + w * 800 + lane * PATCH;   // stride 25: CF
            float* wrow = wbil + lane * WPAD + w * NACT;
#pragma unroll
            for (int pa = 0; pa < NACT; ++pa) {
                const int4   q = qtab[oo * NACT + pa];   // broadcast
                const float4 c = ctab[oo * NACT + pa];   // broadcast
                float v;
                v = c.x * srow[q.x];
                v = fmaf(c.y, srow[q.y], v);
                v = fmaf(c.z, srow[q.z], v);
                v = fmaf(c.w, srow[q.w], v);
                wrow[pa] = v;                            // stride 105: CF
            }
        }
        __syncthreads();

        // ---- (c) phase BC: rc-outer, table-driven, hoisted cj pointers ----
        {
            const float* wr0 = wbil + (w +  0) * WPAD;
            const float* wr1 = wbil + (w +  8) * WPAD;
            const float* wr2 = wbil + (w + 16) * WPAD;
            const float* wr3 = wbil + (w + 24) * WPAD;
            float* ob = out + (size_t)ci_base * OUT_CI_STRIDE
                            + (size_t)((o_base + oo) * C_DIM + co) * 200
                            + (size_t)w * OUT_CI_STRIDE;
            float* o0p = ob;
            float* o1p = ob + (size_t)8  * OUT_CI_STRIDE;
            float* o2p = ob + (size_t)16 * OUT_CI_STRIDE;
            float* o3p = ob + (size_t)24 * OUT_CI_STRIDE;

#pragma unroll
            for (int rc = 0; rc < 7; ++rc) {
                const int r = rc * 32 + lane;
                if (r < 200) {
                    const float    fr = frtab[r];
                    const unsigned pk = offtab[r];
                    const int a0 = pk & 255;
                    const int a1 = (pk >> 8) & 255;
                    if (pk >> 16) {
                        float v0, v1;
                        v0 = wr0[a0]; v1 = wr0[a1];
                        o0p[r] = fmaf(fr, v1 - v0, v0);
                        v0 = wr1[a0]; v1 = wr1[a1];
                        o1p[r] = fmaf(fr, v1 - v0, v0);
                        v0 = wr2[a0]; v1 = wr2[a1];
                        o2p[r] = fmaf(fr, v1 - v0, v0);
                        v0 = wr3[a0]; v1 = wr3[a1];
                        o3p[r] = fmaf(fr, v1 - v0, v0);
                    } else {
                        o0p[r] = 0.0f; o1p[r] = 0.0f;
                        o2p[r] = 0.0f; o3p[r] = 0.0f;
                    }
                }
            }
        }
        __syncthreads();   // wbil + tables reused next oo
    }
}

extern "C" void kernel_launch(void* const* d_in, const int* in_sizes, int n_in,
                              void* d_out, int out_size)
{
    const float* in_H   = (const float*)d_in[0];
    const float* out_H  = (const float*)d_in[1];
    const float* weight = (const float*)d_in[2];
    float* out = (float*)d_out;

    dim3 grid(C_DIM, C_DIM / CIN_CHUNK, NROT / OGRP);   // 1024 blocks
    gk_r11_kernel<<<grid, TPB>>>(in_H, out_H, weight, out);
}

// round 14
// speedup vs baseline: 1.3465x; 1.1665x over previous
#include <cuda_runtime.h>

#define TWO_PI_F 6.283185307179586f
#define NROT 8
#define C_DIM 128
#define KS 5
#define PATCH 25
#define TPB 416                     // 13 warps = one per active tap
#define NWARP 13
#define CIN_CHUNK 32
#define NACT 13
#define OGRP 4
#define ACT_MASK 0x477DC4u          // bit p set iff X^2+Y^2 <= 1 on 5x5 grid
#define OUT_CI_STRIDE (NROT * C_DIM * 200)   // 204800
#define SPAD 33                     // stage [r200][ci32] row stride (CF both ways)

__device__ __constant__ int APLIST[NACT] = {2,6,7,8,10,11,12,13,14,16,17,18,22};

__device__ __forceinline__ unsigned smem_u32(const void* p) {
    return (unsigned)__cvta_generic_to_shared(p);
}

__global__ __launch_bounds__(TPB)
void gk_r12_kernel(const float* __restrict__ in_H,
                   const float* __restrict__ out_H,
                   const float* __restrict__ weight,
                   float* __restrict__ out)
{
    __shared__ float  slab[NROT * 800];        // 25.6 KB [g][ci32][q25]
    __shared__ float  stage[200 * SPAD];       // 26.4 KB [r][ci], pad 33
    __shared__ float  c8[OGRP * 64];           // [oo][g][i] Gk-mix coefficients
    __shared__ float4 ctab[OGRP * NACT];       // bilinear corner weights
    __shared__ int4   qtab[OGRP * NACT];       // bilinear corner indices

    const int co      = blockIdx.x;
    const int ci_base = blockIdx.y * CIN_CHUNK;
    const int o_base  = blockIdx.z * OGRP;
    const int tid     = threadIdx.x;
    const int w       = tid >> 5;      // warp = pa (phase A), row-group (store)
    const int lane    = tid & 31;      // lane = ci (phase A), r-chunk (store)

    // ---- fill slab with cp.async ----
    {
        const float4* __restrict__ w4 = (const float4*)weight;
#pragma unroll
        for (int k = 0; k < 4; ++k) {
            int f = tid + k * TPB;                   // float4 index 0..1599
            if (f < 1600) {
                int g = f / 200;
                int r = f - g * 200;
                size_t gb4 = ((size_t)((g * C_DIM + co) * C_DIM + ci_base) * PATCH) >> 2;
                unsigned dst = smem_u32(&slab[g * 800 + r * 4]);
                asm volatile("cp.async.cg.shared.global [%0], [%1], 16;\n"
                             :: "r"(dst), "l"(w4 + gb4 + r) : "memory");
            }
        }
        asm volatile("cp.async.commit_group;\n" ::: "memory");
    }

    // ---- zero stage once: inactive rows stay 0 for all oo ----
    for (int z = tid; z < 200 * SPAD; z += TPB) stage[z] = 0.0f;

    // ---- Gk-mix coefficient matrix c8[oo][g][i] (self-contained, no dependency) ----
    if (tid < OGRP * 64) {
        const int oo = tid >> 6, g = (tid >> 3) & 7, i = tid & 7;
        const float outH  = out_H[o_base + oo];
        const float theta = in_H[i] - outH;
        const float tmod  = theta - floorf(theta * (1.0f / TWO_PI_F)) * TWO_PI_F;
        const float pos   = tmod * ((float)NROT / TWO_PI_F);
        int g0 = ((int)floorf(pos)) % NROT;
        if (g0 >= NROT) g0 -= NROT;
        const int g1 = (g0 + 1) & (NROT - 1);
        const float frac = pos - floorf(pos);
        float c = 0.0f;
        if (g == g0) c += 1.0f - frac;
        if (g == g1) c += frac;
        c8[tid] = c;
    }

    // ---- per-(oo,pa) bilinear tables ----
    if (tid < OGRP * NACT) {
        const int oo = tid / NACT, pa = tid - oo * NACT;
        const int p  = APLIST[pa];
        const int px = p % KS, py = p / KS;
        const float X = -1.0f + 0.5f * (float)px;
        const float Y = -1.0f + 0.5f * (float)py;
        const float outH = out_H[o_base + oo];
        const float cc = cosf(-outH), ss = sinf(-outH);
        const float gx = cc * X - ss * Y;
        const float gy = ss * X + cc * Y;
        const float sx = fmaf(gx, 2.0f, 2.0f);
        const float sy = fmaf(gy, 2.0f, 2.0f);
        const float fxf = floorf(sx), fyf = floorf(sy);
        const float fx = sx - fxf, fy = sy - fyf;
        int x0 = min(max((int)fxf, 0), KS - 1);
        int y0 = min(max((int)fyf, 0), KS - 1);
        const int x1 = min(x0 + 1, KS - 1);
        const int y1 = min(y0 + 1, KS - 1);
        ctab[tid] = make_float4((1.0f - fy) * (1.0f - fx), (1.0f - fy) * fx,
                                fy * (1.0f - fx),          fy * fx);
        qtab[tid] = make_int4(y0 * KS + x0, y0 * KS + x1,
                              y1 * KS + x0, y1 * KS + x1);
    }

    const int p = APLIST[w];       // this warp's tap (w < 13 always)

    asm volatile("cp.async.wait_group 0;\n" ::: "memory");
    __syncthreads();

    for (int oo = 0; oo < OGRP; ++oo) {
        // ---- phase A: per-thread (pa=w, ci=lane): 8-g bilinear + register Gk mix ----
        {
            const int4   q  = qtab[oo * NACT + w];   // broadcast
            const float4 cw = ctab[oo * NACT + w];   // broadcast
            const float* sb = slab + lane * PATCH;   // lanes stride 25: CF

            float a0 = 0.f, a1 = 0.f, a2 = 0.f, a3 = 0.f;
            float a4 = 0.f, a5 = 0.f, a6 = 0.f, a7 = 0.f;
#pragma unroll
            for (int g = 0; g < NROT; ++g) {
                const float* sg = sb + g * 800;
                float v;
                v = cw.x * sg[q.x];
                v = fmaf(cw.y, sg[q.y], v);
                v = fmaf(cw.z, sg[q.z], v);
                v = fmaf(cw.w, sg[q.w], v);
                const float4 ca = *(const float4*)&c8[oo * 64 + g * 8];     // broadcast
                const float4 cb = *(const float4*)&c8[oo * 64 + g * 8 + 4]; // broadcast
                a0 = fmaf(ca.x, v, a0); a1 = fmaf(ca.y, v, a1);
                a2 = fmaf(ca.z, v, a2); a3 = fmaf(ca.w, v, a3);
                a4 = fmaf(cb.x, v, a4); a5 = fmaf(cb.y, v, a5);
                a6 = fmaf(cb.z, v, a6); a7 = fmaf(cb.w, v, a7);
            }
            // stage[(i*25+p)][ci]: lanes consecutive -> CF
            stage[(0 * PATCH + p) * SPAD + lane] = a0;
            stage[(1 * PATCH + p) * SPAD + lane] = a1;
            stage[(2 * PATCH + p) * SPAD + lane] = a2;
            stage[(3 * PATCH + p) * SPAD + lane] = a3;
            stage[(4 * PATCH + p) * SPAD + lane] = a4;
            stage[(5 * PATCH + p) * SPAD + lane] = a5;
            stage[(6 * PATCH + p) * SPAD + lane] = a6;
            stage[(7 * PATCH + p) * SPAD + lane] = a7;
        }
        __syncthreads();

        // ---- store: row ci = w, w+13, w+26; lanes span r (CF LDS, coalesced STG) ----
        {
#pragma unroll
            for (int rowk = 0; rowk < 3; ++rowk) {
                const int ci = w + rowk * NWARP;
                if (ci < CIN_CHUNK) {
                    const float* srow = stage + ci;        // addr = r*33 + ci
                    float* orow = out + (size_t)(ci_base + ci) * OUT_CI_STRIDE
                                      + (size_t)((o_base + oo) * C_DIM + co) * 200;
#pragma unroll
                    for (int rc = 0; rc < 7; ++rc) {
                        const int r = rc * 32 + lane;
                        if (r < 200)
                            orow[r] = srow[r * SPAD];      // stride 33: CF; STG coalesced
                    }
                }
            }
        }
        __syncthreads();   // stage reused next oo
    }
}

extern "C" void kernel_launch(void* const* d_in, const int* in_sizes, int n_in,
                              void* d_out, int out_size)
{
    const float* in_H   = (const float*)d_in[0];
    const float* out_H  = (const float*)d_in[1];
    const float* weight = (const float*)d_in[2];
    float* out = (float*)d_out;

    dim3 grid(C_DIM, C_DIM / CIN_CHUNK, NROT / OGRP);   // 1024 blocks
    gk_r12_kernel<<<grid, TPB>>>(in_H, out_H, weight, out);
}